// round 4
// baseline (speedup 1.0000x reference)
#include <cuda_runtime.h>

// out[b,j] = input2[b,j] * sum_i input1[b,i] * w2[i,j],  w2 = weights.sum(axis=2)
// B=16384, I=64, J=2048, K=64. All fp32.
//
// K-in-lanes FFMA2 scheme: f32x2 lanes carry (even i, odd i) partial sums.
// No operand duplication; horizontal add in epilogue.

#define B_DIM 16384
#define I_DIM 64
#define J_DIM 2048
#define K_DIM 64
#define I2    32        // I/2 pair-steps

// Paired K-reduced weights: g_w2p[i2*J + j] = {w2[2*i2][j], w2[2*i2+1][j]}
__device__ unsigned long long g_w2p[I2 * J_DIM];

// ---------------------------------------------------------------------------
// Kernel 1: w2[i,j] = sum_k weights[i,j,k], written in i-paired layout.
// One warp per (i,j). 131072 warps.
// ---------------------------------------------------------------------------
__global__ void reduce_w_kernel(const float* __restrict__ w) {
    int gw   = (blockIdx.x * blockDim.x + threadIdx.x) >> 5;  // i*J + j
    int lane = threadIdx.x & 31;
    const float* p = w + (size_t)gw * K_DIM;
    float s = p[lane] + p[lane + 32];
    #pragma unroll
    for (int o = 16; o > 0; o >>= 1)
        s += __shfl_down_sync(0xffffffffu, s, o);
    if (lane == 0) {
        int i = gw >> 11;         // / J_DIM
        int j = gw & (J_DIM - 1);
        ((float*)g_w2p)[((size_t)(i >> 1) * J_DIM + j) * 2 + (i & 1)] = s;
    }
}

// ---------------------------------------------------------------------------
// Kernel 2: fused GEMM + multiply. 256 threads, tile 128(B) x 128(J),
// thread tile 8 rows x 8 cols, acc = 64 f32x2 (i-parity split).
// ---------------------------------------------------------------------------
__device__ __forceinline__ unsigned long long ffma2(unsigned long long a,
                                                    unsigned long long b,
                                                    unsigned long long c) {
    unsigned long long d;
    asm("fma.rn.f32x2 %0, %1, %2, %3;" : "=l"(d) : "l"(a), "l"(b), "l"(c));
    return d;
}

#define S1 130          // x1p row stride in ull (even: 16B-aligned LDS.128; 130%16!=0)

__global__ void __launch_bounds__(256, 1)
gemm_mul_kernel(const float* __restrict__ x1,
                const float* __restrict__ x2,
                float* __restrict__ out) {
    extern __shared__ char smem_raw[];
    unsigned long long* x1p = (unsigned long long*)smem_raw;      // [32][130]: {x1[b][2i2],x1[b][2i2+1]}
    uint4* w2p = (uint4*)(smem_raw + I2 * S1 * 8);                // [32][64] 16B units, sigma-swizzled

    const int tid = threadIdx.x;
    const int tx  = tid & 15;       // j direction
    const int ty  = tid >> 4;       // b direction
    const int j0  = blockIdx.x * 128;
    const int b0  = blockIdx.y * 128;

    // ---- Fill w2p tile (2048 16B units), swizzle sigma(m) = (m&3)*16 + (m>>2) ----
    // Unit m of row i2 holds cols {j0+2m, j0+2m+1}. After sigma, thread tx owns
    // contiguous cols [8tx, 8tx+8) via slots {c*16+tx : c=0..3}.
    #pragma unroll
    for (int k = 0; k < 8; k++) {
        int idx = tid + k * 256;
        int i2  = idx >> 6;
        int m   = idx & 63;
        uint4 v = *(const uint4*)(&g_w2p[(size_t)i2 * J_DIM + j0 + m * 2]);
        int sl  = ((m & 3) << 4) + (m >> 2);
        w2p[i2 * 64 + sl] = v;
    }
    // ---- Fill x1p tile: natural i-pairs, transposed to [i2][b] ----
    #pragma unroll
    for (int k = 0; k < 8; k++) {
        int idx = tid + k * 256;          // 128 b x 16 u
        int b   = idx & 127;
        int u   = idx >> 7;               // float4 group: pairs 2u, 2u+1
        ulonglong2 v = *(const ulonglong2*)(&x1[(size_t)(b0 + b) * I_DIM + u * 4]);
        x1p[(2 * u + 0) * S1 + b] = v.x;
        x1p[(2 * u + 1) * S1 + b] = v.y;
    }
    __syncthreads();

    // ---- Mainloop: 32 i2-steps, 64 FFMA2 each ----
    unsigned long long acc[8][8];
    #pragma unroll
    for (int r = 0; r < 8; r++)
        #pragma unroll
        for (int q = 0; q < 8; q++) acc[r][q] = 0ull;

    const int arow = ty * 8;

    #pragma unroll 2
    for (int i2 = 0; i2 < I2; i2++) {
        unsigned long long a[8];
        {   // 4x LDS.128, broadcast (2 addrs/warp)
            ulonglong2 t0 = *(const ulonglong2*)(&x1p[i2 * S1 + arow + 0]);
            ulonglong2 t1 = *(const ulonglong2*)(&x1p[i2 * S1 + arow + 2]);
            ulonglong2 t2 = *(const ulonglong2*)(&x1p[i2 * S1 + arow + 4]);
            ulonglong2 t3 = *(const ulonglong2*)(&x1p[i2 * S1 + arow + 6]);
            a[0] = t0.x; a[1] = t0.y; a[2] = t1.x; a[3] = t1.y;
            a[4] = t2.x; a[5] = t2.y; a[6] = t3.x; a[7] = t3.y;
        }
        unsigned long long b[8];
        #pragma unroll
        for (int c = 0; c < 4; c++) {     // 4x LDS.128, 16 consecutive units -> 2 wf
            ulonglong2 bb = *(const ulonglong2*)(&w2p[i2 * 64 + c * 16 + tx]);
            b[2 * c + 0] = bb.x;          // col j0 + 8tx + 2c
            b[2 * c + 1] = bb.y;          // col j0 + 8tx + 2c + 1
        }
        #pragma unroll
        for (int r = 0; r < 8; r++)
            #pragma unroll
            for (int q = 0; q < 8; q++)
                acc[r][q] = ffma2(a[r], b[q], acc[r][q]);
    }

    // ---- Epilogue: horizontal add lanes, multiply by x2, float4 stores ----
    const int bcol = tx * 8;
    #pragma unroll
    for (int r = 0; r < 8; r++) {
        size_t row = (size_t)(b0 + arow + r) * J_DIM + j0 + bcol;
        float4 xa = *(const float4*)(&x2[row]);
        float4 xb = *(const float4*)(&x2[row + 4]);
        float o[8];
        #pragma unroll
        for (int q = 0; q < 8; q++) {
            float lo = __uint_as_float((unsigned)acc[r][q]);
            float hi = __uint_as_float((unsigned)(acc[r][q] >> 32));
            o[q] = lo + hi;
        }
        float4 o0 = make_float4(o[0] * xa.x, o[1] * xa.y, o[2] * xa.z, o[3] * xa.w);
        float4 o1 = make_float4(o[4] * xb.x, o[5] * xb.y, o[6] * xb.z, o[7] * xb.w);
        *(float4*)(&out[row])     = o0;
        *(float4*)(&out[row + 4]) = o1;
    }
}

// ---------------------------------------------------------------------------
extern "C" void kernel_launch(void* const* d_in, const int* in_sizes, int n_in,
                              void* d_out, int out_size) {
    const float* x1 = (const float*)d_in[0];  // (B, I)
    const float* x2 = (const float*)d_in[1];  // (B, J)
    const float* w  = (const float*)d_in[2];  // (I, J, K)
    float* out      = (float*)d_out;          // (B, J)

    reduce_w_kernel<<<(I_DIM * J_DIM) / 8, 256>>>(w);

    const int smem_bytes = I2 * S1 * 8        // x1p: 33280
                         + I2 * 64 * 16;      // w2p: 32768
    cudaFuncSetAttribute(gemm_mul_kernel,
                         cudaFuncAttributeMaxDynamicSharedMemorySize, smem_bytes);
    dim3 grid(J_DIM / 128, B_DIM / 128);      // (16, 128)
    gemm_mul_kernel<<<grid, 256, smem_bytes>>>(x1, x2, out);
}

// round 5
// speedup vs baseline: 1.7786x; 1.7786x over previous
#include <cuda_runtime.h>
#include <cstdint>

// out[b,j] = input2[b,j] * sum_i input1[b,i] * w2[i,j],  w2 = weights.sum(axis=2)
// B=16384, I=64, J=2048, K=64. fp32 in/out; GEMM inner product in tf32 mma.sync.

#define B_DIM 16384
#define I_DIM 64
#define J_DIM 2048
#define K_DIM 64

// K-reduced weights, stored as tf32-rounded fp32 bit patterns.
__device__ float g_w2[I_DIM * J_DIM];

__device__ __forceinline__ uint32_t f32_to_tf32(float f) {
    uint32_t t;
    asm("cvt.rna.tf32.f32 %0, %1;" : "=r"(t) : "f"(f));
    return t;
}

// ---------------------------------------------------------------------------
// Kernel 1: w2[i,j] = sum_k weights[i,j,k] (fp32), rounded to tf32 at store.
// ---------------------------------------------------------------------------
__global__ void reduce_w_kernel(const float* __restrict__ w) {
    int gw   = (blockIdx.x * blockDim.x + threadIdx.x) >> 5;  // i*J + j
    int lane = threadIdx.x & 31;
    const float* p = w + (size_t)gw * K_DIM;
    float s = p[lane] + p[lane + 32];
    #pragma unroll
    for (int o = 16; o > 0; o >>= 1)
        s += __shfl_down_sync(0xffffffffu, s, o);
    if (lane == 0) g_w2[gw] = __uint_as_float(f32_to_tf32(s));
}

// ---------------------------------------------------------------------------
// Kernel 2: tf32 tensor-core GEMM (x1 @ w2) * x2.
// Tile 128(B) x 128(J), K=64 resident. 8 warps; warp tile 32x64
// (2 m16 frags x 8 n8 frags, 8 k8 steps). mma.sync.m16n8k8.tf32.
// ---------------------------------------------------------------------------
#define SA 68    // x1s row stride (floats): bank = (4*row + col) % 32, conflict-free
#define SB 136   // w2s row stride (floats): bank = (8*k + n) % 32, conflict-free

__device__ __forceinline__ void mma_tf32(float* d, const uint32_t* a,
                                         uint32_t b0, uint32_t b1) {
    asm volatile(
        "mma.sync.aligned.m16n8k8.row.col.f32.tf32.tf32.f32 "
        "{%0,%1,%2,%3}, {%4,%5,%6,%7}, {%8,%9}, {%0,%1,%2,%3};"
        : "+f"(d[0]), "+f"(d[1]), "+f"(d[2]), "+f"(d[3])
        : "r"(a[0]), "r"(a[1]), "r"(a[2]), "r"(a[3]), "r"(b0), "r"(b1));
}

__global__ void __launch_bounds__(256, 2)
gemm_mul_kernel(const float* __restrict__ x1,
                const float* __restrict__ x2,
                float* __restrict__ out) {
    extern __shared__ float smem[];
    float* x1s = smem;                 // [128][SA] tf32 bits
    float* w2s = smem + 128 * SA;      // [64][SB]  tf32 bits

    const int tid    = threadIdx.x;
    const int wid    = tid >> 5;
    const int lane   = tid & 31;
    const int g      = lane >> 2;      // groupID 0..7
    const int tq     = lane & 3;       // thread-in-group 0..3
    const int warp_m = wid & 3;        // M: 4 warps x 32 rows
    const int warp_n = wid >> 2;       // N: 2 warps x 64 cols
    const int j0     = blockIdx.x * 128;
    const int b0     = blockIdx.y * 128;

    // ---- Fill x1s [128 x 64], tf32-convert. Row fast across lanes:
    // STS.128 phases hit 16B-units 17*r mod 32 (r=0..7) -> conflict-free.
    #pragma unroll
    for (int k = 0; k < 8; k++) {
        int idx = tid + k * 256;             // 128 rows x 16 float4
        int r   = idx & 127;
        int u   = idx >> 7;
        float4 v = *(const float4*)(&x1[(size_t)(b0 + r) * I_DIM + u * 4]);
        float4 o;
        o.x = __uint_as_float(f32_to_tf32(v.x));
        o.y = __uint_as_float(f32_to_tf32(v.y));
        o.z = __uint_as_float(f32_to_tf32(v.z));
        o.w = __uint_as_float(f32_to_tf32(v.w));
        *(float4*)(&x1s[r * SA + u * 4]) = o;
    }
    // ---- Fill w2s [64 x 128] (already tf32 from reduce kernel) ----
    #pragma unroll
    for (int k = 0; k < 8; k++) {
        int idx = tid + k * 256;             // 64 rows x 32 float4
        int i   = idx >> 5;
        int c4  = idx & 31;
        float4 v = *(const float4*)(&g_w2[(size_t)i * J_DIM + j0 + c4 * 4]);
        *(float4*)(&w2s[i * SB + c4 * 4]) = v;
    }
    __syncthreads();

    float acc[2][8][4];
    #pragma unroll
    for (int m = 0; m < 2; m++)
        #pragma unroll
        for (int n = 0; n < 8; n++)
            #pragma unroll
            for (int q = 0; q < 4; q++) acc[m][n][q] = 0.0f;

    const int arow = warp_m * 32;
    const int bcol = warp_n * 64;

    #pragma unroll
    for (int k0 = 0; k0 < K_DIM; k0 += 8) {
        // A fragments: a0(r=g), a1(r=g+8), a2(r=g, c+4), a3(r=g+8, c+4)
        uint32_t A[2][4];
        #pragma unroll
        for (int m = 0; m < 2; m++) {
            int r0 = arow + m * 16 + g;
            int r1 = r0 + 8;
            A[m][0] = __float_as_uint(x1s[r0 * SA + k0 + tq]);
            A[m][1] = __float_as_uint(x1s[r1 * SA + k0 + tq]);
            A[m][2] = __float_as_uint(x1s[r0 * SA + k0 + tq + 4]);
            A[m][3] = __float_as_uint(x1s[r1 * SA + k0 + tq + 4]);
        }
        #pragma unroll
        for (int n = 0; n < 8; n++) {
            int col = bcol + n * 8 + g;
            uint32_t B0 = __float_as_uint(w2s[(k0 + tq) * SB + col]);
            uint32_t B1 = __float_as_uint(w2s[(k0 + tq + 4) * SB + col]);
            mma_tf32(acc[0][n], A[0], B0, B1);
            mma_tf32(acc[1][n], A[1], B0, B1);
        }
    }

    // ---- Epilogue: multiply by x2, float2 stores.
    // d0/d1 at (row, 2tq(+1)); d2/d3 at (row+8, 2tq(+1)).
    #pragma unroll
    for (int m = 0; m < 2; m++) {
        int r0 = b0 + arow + m * 16 + g;
        #pragma unroll
        for (int n = 0; n < 8; n++) {
            int c = j0 + bcol + n * 8 + tq * 2;
            size_t o0 = (size_t)r0 * J_DIM + c;
            size_t o1 = o0 + (size_t)8 * J_DIM;
            float2 xa = *(const float2*)(&x2[o0]);
            float2 xb = *(const float2*)(&x2[o1]);
            float2 ra, rb;
            ra.x = acc[m][n][0] * xa.x;
            ra.y = acc[m][n][1] * xa.y;
            rb.x = acc[m][n][2] * xb.x;
            rb.y = acc[m][n][3] * xb.y;
            *(float2*)(&out[o0]) = ra;
            *(float2*)(&out[o1]) = rb;
        }
    }
}

// ---------------------------------------------------------------------------
extern "C" void kernel_launch(void* const* d_in, const int* in_sizes, int n_in,
                              void* d_out, int out_size) {
    const float* x1 = (const float*)d_in[0];  // (B, I)
    const float* x2 = (const float*)d_in[1];  // (B, J)
    const float* w  = (const float*)d_in[2];  // (I, J, K)
    float* out      = (float*)d_out;          // (B, J)

    reduce_w_kernel<<<(I_DIM * J_DIM) / 8, 256>>>(w);

    const int smem_bytes = (128 * SA + 64 * SB) * 4;   // 69632 B
    cudaFuncSetAttribute(gemm_mul_kernel,
                         cudaFuncAttributeMaxDynamicSharedMemorySize, smem_bytes);
    dim3 grid(J_DIM / 128, B_DIM / 128);               // (16, 128)
    gemm_mul_kernel<<<grid, 256, smem_bytes>>>(x1, x2, out);
}